// round 6
// baseline (speedup 1.0000x reference)
#include <cuda_runtime.h>
#include <cuda_fp16.h>

// Problem constants
#define NB 16            // batch B
#define TT 12            // T_IN
#define TO 24            // T_TOTAL
#define NN 5000          // nodes
#define CC 4             // channels
#define KK 16            // neighbors
#define HH 4             // heads
#define BT (NB * TT)     // 192
#define BTP (BT / 2)     // 96 bt-pairs
#define DIN (TT * HH)    // 48
#define DOUT (TO - TT)   // 12
#define NT 2             // nodes per block
#define THREADS 192

// agg shared layout: per b-group, row stride 20 floats (80B, 16B aligned),
// b stride 244 (mod 32 = 20), node stride 3920 (mod 32 = 16).
#define AGG_B 244                    // floats per b-group
#define AGG_NL (NB * AGG_B + 16)     // 3920 floats per node region

typedef unsigned long long u64;

// Scratch: x transposed+converted to fp16: [N][btp][8 halfs]. 7.68 MB, L2-resident.
__device__ uint4 g_xt[NN * BTP];

static __device__ __forceinline__ float2 h2f(unsigned u) {
    __half2 h = *reinterpret_cast<__half2*>(&u);
    return __half22float2(h);
}
// pack two floats into a 64-bit f32x2 operand
static __device__ __forceinline__ u64 pk(float lo, float hi) {
    u64 r;
    asm("mov.b64 %0, {%1, %2};" : "=l"(r) : "f"(lo), "f"(hi));
    return r;
}
// packed dual-FMA: d.lo = a.lo*b.lo + c.lo ; d.hi = a.hi*b.hi + c.hi  (full fp32)
static __device__ __forceinline__ u64 fma2(u64 a, u64 b, u64 c) {
    u64 d;
    asm("fma.rn.f32x2 %0, %1, %2, %3;" : "=l"(d) : "l"(a), "l"(b), "l"(c));
    return d;
}
static __device__ __forceinline__ float2 upk(u64 v) {
    float2 f;
    asm("mov.b64 {%0, %1}, %2;" : "=f"(f.x), "=f"(f.y) : "l"(v));
    return f;
}

// ---------------------------------------------------------------------------
// Kernel 1: x [B,T,N,C] f32 -> xt [N][btp] fp16 (transposed)  AND out[:, :12] = x
// ---------------------------------------------------------------------------
__global__ void __launch_bounds__(1024) transpose_convert_kernel(
    const float* __restrict__ x, float* __restrict__ out)
{
    __shared__ uint2 tile[32][33];
    const float4* __restrict__ x4 = (const float4*)x;
    float4* __restrict__ out4 = (float4*)out;

    int tx = threadIdx.x, ty = threadIdx.y;
    int n  = blockIdx.x * 32 + tx;
    int bt = blockIdx.y * 32 + ty;          // gridDim.y*32 == 192 exactly

    if (n < NN) {
        float4 v = x4[bt * NN + n];
        __half2 h01 = __floats2half2_rn(v.x, v.y);
        __half2 h23 = __floats2half2_rn(v.z, v.w);
        uint2 u;
        u.x = *reinterpret_cast<unsigned*>(&h01);
        u.y = *reinterpret_cast<unsigned*>(&h23);
        tile[ty][tx] = u;
        int b = bt / TT, t = bt - b * TT;
        out4[(b * TO + t) * NN + n] = v;    // out[:, :12] = x (coalesced)
    }
    __syncthreads();

    if (tx < 16) {
        int n2 = blockIdx.x * 32 + ty;
        if (n2 < NN) {
            int btp = blockIdx.y * 16 + tx;
            uint2 a  = tile[2 * tx][ty];
            uint2 b2 = tile[2 * tx + 1][ty];
            g_xt[n2 * BTP + btp] = make_uint4(a.x, a.y, b2.x, b2.y);
        }
    }
}

// ---------------------------------------------------------------------------
// Kernel 2: per node-pair, packed-f32x2 math throughout.
//   phase 1: thread = (nl, btp)   -> fp16 gather + weighted agg (f32x2 accum)
//   phase 2: thread = (nl, b, op) -> 48x12 matmul (o-pair), ReLU, store
// ---------------------------------------------------------------------------
__global__ void __launch_bounds__(THREADS, 5) gnn_main_kernel(
    const float* __restrict__ dists, const int* __restrict__ neighbors,
    const float* __restrict__ W, const float* __restrict__ bias,
    float* __restrict__ out)
{
    __shared__ __align__(16) float agg_s[NT * AGG_NL];
    __shared__ ulonglong2 wp_s[NT][KK][2];       // [(w0,w0),(w1,w1)],[(w2,w2),(w3,w3)]
    __shared__ ulonglong2 Wpk_s[DIN * 6];        // [(t,h)][op] -> {(wo0,wo0),(wo1,wo1)}
    __shared__ int   nbr_s[NT][KK];
    __shared__ float b_s[DOUT];

    const int tid = threadIdx.x;             // 0..191
    const int n0  = blockIdx.x * NT;

    // --- Phase 0: exp weights (pre-broadcast packed), neighbors, W packed, bias ---
    if (tid < NT * KK) {
        int nl = tid >> 4, k = tid & 15;
        float d = dists[(n0 + nl) * KK + k];
        nbr_s[nl][k] = neighbors[(n0 + nl) * KK + k];
        float p = d * d * (1.0f / 36.0f);    // d^2 / sigma^2
        float w0 = __expf(-0.25f * p);
        float w1 = __expf(-0.50f * p);
        float w2 = __expf(-0.75f * p);
        float w3 = __expf(-p);
        wp_s[nl][k][0] = make_ulonglong2(pk(w0, w0), pk(w1, w1));
        wp_s[nl][k][1] = make_ulonglong2(pk(w2, w2), pk(w3, w3));
    }
    #pragma unroll
    for (int i = tid; i < DIN * 6; i += THREADS) {
        int th = i / 6, op = i - th * 6;
        float w0 = W[th * DOUT + op * 2];
        float w1 = W[th * DOUT + op * 2 + 1];
        Wpk_s[i] = make_ulonglong2(pk(w0, w0), pk(w1, w1));
    }
    if (tid < DOUT) b_s[tid] = bias[tid];
    __syncthreads();

    // --- Phase 1: fp16 gather + packed weighted aggregation ---
    {
        const int nl  = tid / BTP;               // warp-uniform
        const int btp = tid - nl * BTP;
        const int bt0 = btp * 2;
        const int b0 = bt0 / TT, t0 = bt0 - b0 * TT;   // t0 even; t1 = t0+1 same b

        u64 acc[2][HH][2];                        // [bt][h][c01|c23]
        #pragma unroll
        for (int p = 0; p < 2; ++p)
            #pragma unroll
            for (int h = 0; h < HH; ++h) {
                acc[p][h][0] = 0ULL; acc[p][h][1] = 0ULL;
            }

        #pragma unroll
        for (int k = 0; k < KK; ++k) {
            uint4 raw = g_xt[nbr_s[nl][k] * BTP + btp];
            float2 p00 = h2f(raw.x);   // bt0: c0,c1
            float2 p01 = h2f(raw.y);   // bt0: c2,c3
            float2 p10 = h2f(raw.z);   // bt1: c0,c1
            float2 p11 = h2f(raw.w);   // bt1: c2,c3
            u64 x00 = pk(p00.x, p00.y);
            u64 x01 = pk(p01.x, p01.y);
            u64 x10 = pk(p10.x, p10.y);
            u64 x11 = pk(p11.x, p11.y);
            ulonglong2 wA = wp_s[nl][k][0];   // (w0,w0),(w1,w1)
            ulonglong2 wB = wp_s[nl][k][1];   // (w2,w2),(w3,w3)
            acc[0][0][0] = fma2(x00, wA.x, acc[0][0][0]);
            acc[0][0][1] = fma2(x01, wA.x, acc[0][0][1]);
            acc[0][1][0] = fma2(x00, wA.y, acc[0][1][0]);
            acc[0][1][1] = fma2(x01, wA.y, acc[0][1][1]);
            acc[0][2][0] = fma2(x00, wB.x, acc[0][2][0]);
            acc[0][2][1] = fma2(x01, wB.x, acc[0][2][1]);
            acc[0][3][0] = fma2(x00, wB.y, acc[0][3][0]);
            acc[0][3][1] = fma2(x01, wB.y, acc[0][3][1]);
            acc[1][0][0] = fma2(x10, wA.x, acc[1][0][0]);
            acc[1][0][1] = fma2(x11, wA.x, acc[1][0][1]);
            acc[1][1][0] = fma2(x10, wA.y, acc[1][1][0]);
            acc[1][1][1] = fma2(x11, wA.y, acc[1][1][1]);
            acc[1][2][0] = fma2(x10, wB.x, acc[1][2][0]);
            acc[1][2][1] = fma2(x11, wB.x, acc[1][2][1]);
            acc[1][3][0] = fma2(x10, wB.y, acc[1][3][0]);
            acc[1][3][1] = fma2(x11, wB.y, acc[1][3][1]);
        }
        float* r0 = agg_s + nl * AGG_NL + b0 * AGG_B + t0 * 20;
        #pragma unroll
        for (int h = 0; h < HH; ++h) {
            *(ulonglong2*)(r0 + h * 4) = make_ulonglong2(acc[0][h][0], acc[0][h][1]);
            *(ulonglong2*)(r0 + 20 + h * 4) = make_ulonglong2(acc[1][h][0], acc[1][h][1]);
        }
    }
    __syncthreads();

    // --- Phase 2: y[b,n,c,o] = relu(sum_{t,h} agg[b,t,h,c] * W[t*H+h,o] + b[o])
    // Thread = (nl, op, b). Inner (t,h): LDS.128 + LDS.128 + 4 FMA2.
    {
        const int nl = tid & 1;
        const int r  = tid >> 1;             // 0..95
        const int op = r % 6;                // o-pair: o = 2*op, 2*op+1
        const int b  = r / 6;                // 0..15

        float bv0 = b_s[op * 2], bv1 = b_s[op * 2 + 1];
        u64 acc00 = pk(bv0, bv0), acc01 = acc00;   // o0: c01, c23
        u64 acc10 = pk(bv1, bv1), acc11 = acc10;   // o1: c01, c23

        const float* abase = agg_s + nl * AGG_NL + b * AGG_B;
        const ulonglong2* wb = Wpk_s + op;
        #pragma unroll
        for (int t = 0; t < TT; ++t) {
            #pragma unroll
            for (int h = 0; h < HH; ++h) {
                ulonglong2 a = *(const ulonglong2*)(abase + t * 20 + h * 4);
                ulonglong2 w = wb[(t * HH + h) * 6];
                acc00 = fma2(a.x, w.x, acc00);
                acc01 = fma2(a.y, w.x, acc01);
                acc10 = fma2(a.x, w.y, acc10);
                acc11 = fma2(a.y, w.y, acc11);
            }
        }

        float2 f00 = upk(acc00), f01 = upk(acc01);
        float2 f10 = upk(acc10), f11 = upk(acc11);
        float4 y0, y1;
        y0.x = fmaxf(f00.x, 0.f); y0.y = fmaxf(f00.y, 0.f);
        y0.z = fmaxf(f01.x, 0.f); y0.w = fmaxf(f01.y, 0.f);
        y1.x = fmaxf(f10.x, 0.f); y1.y = fmaxf(f10.y, 0.f);
        y1.z = fmaxf(f11.x, 0.f); y1.w = fmaxf(f11.y, 0.f);

        float4* __restrict__ out4 = (float4*)out;
        int o0 = op * 2;
        out4[(b * TO + TT + o0) * NN + (n0 + nl)] = y0;
        out4[(b * TO + TT + o0 + 1) * NN + (n0 + nl)] = y1;
    }
}

// ---------------------------------------------------------------------------
// metadata order: x (f32), dists (f32), W (f32), b (f32), neighbors (i32);
// output f32 (7680000)
// ---------------------------------------------------------------------------
extern "C" void kernel_launch(void* const* d_in, const int* in_sizes, int n_in,
                              void* d_out, int out_size)
{
    const float* x         = (const float*)d_in[0];
    const float* dists     = (const float*)d_in[1];
    const float* W         = (const float*)d_in[2];
    const float* bias      = (const float*)d_in[3];
    const int*   neighbors = (const int*)d_in[4];
    float* out = (float*)d_out;

    dim3 tb(32, 32);
    dim3 tg((NN + 31) / 32, BT / 32);        // 157 x 6
    transpose_convert_kernel<<<tg, tb>>>(x, out);

    gnn_main_kernel<<<NN / NT, THREADS>>>(dists, neighbors, W, bias, out);
}